// round 10
// baseline (speedup 1.0000x reference)
#include <cuda_runtime.h>
#include <cstdint>

#define BB 8
#define TT 4096
#define EE 1024
#define HH 128
#define MM (BB*TT)

// ---------------------------------------------------------------------------
// Scratch (tf32, pre-packed into mma.sync fragment order):
// g_q: per 128-row tile: [rb*16+s][lane][4 words]  (A-frags)
// g_k: per 64-row kv tile: [j*16+s][lane][2 words] (B-frags, kv cols permuted
//      pi(c)=2c / 2(c-4)+1 so the S C-layout equals the PV A-frag order)
// g_v: per 64-row kv tile: [ht*8+skv][lane][2 words]
// g_wp: W B-frags: [by][kc 0..31][J 0..15][s 0..3][lane][2 words]
// ---------------------------------------------------------------------------
static __device__ __align__(16) float g_q[(size_t)MM * HH];
static __device__ __align__(16) float g_k[(size_t)MM * HH];
static __device__ __align__(16) float g_v[(size_t)MM * HH];
static __device__ __align__(16) float g_wp[3u * EE * HH];

__device__ __forceinline__ unsigned f2tf(float f) {
    unsigned u;
    asm("cvt.rna.tf32.f32 %0, %1;" : "=r"(u) : "f"(f));
    return u;
}

__device__ __forceinline__ void mma_tf32(float4& d, const uint4& a, const uint2& b) {
    asm volatile(
        "mma.sync.aligned.m16n8k8.row.col.f32.tf32.tf32.f32 "
        "{%0,%1,%2,%3}, {%4,%5,%6,%7}, {%8,%9}, {%0,%1,%2,%3};"
        : "+f"(d.x), "+f"(d.y), "+f"(d.z), "+f"(d.w)
        : "r"(a.x), "r"(a.y), "r"(a.z), "r"(a.w), "r"(b.x), "r"(b.y));
}

__device__ __forceinline__ void cpasync16(void* sdst, const void* gsrc) {
    unsigned s = (unsigned)__cvta_generic_to_shared(sdst);
    asm volatile("cp.async.cg.shared.global [%0], [%1], 16;" :: "r"(s), "l"(gsrc));
}
#define CP_COMMIT() asm volatile("cp.async.commit_group;")
template <int N> __device__ __forceinline__ void cp_wait() {
    asm volatile("cp.async.wait_group %0;" :: "n"(N));
}

// ---------------------------------------------------------------------------
// Kernel 0: one-shot W pre-pack into B-frag tf32 layout.
// ---------------------------------------------------------------------------
__global__ __launch_bounds__(256) void wpack_kernel(
    const float* __restrict__ Wq, const float* __restrict__ Wk,
    const float* __restrict__ Wv)
{
    const int kc = blockIdx.x;
    const int by = blockIdx.y;
    const float* W = (by == 0) ? Wq : (by == 1) ? Wk : Wv;
    unsigned* dst = (unsigned*)(g_wp + (size_t)by * (EE * HH) + kc * 4096);
    const int t = threadIdx.x;
#pragma unroll
    for (int u = 0; u < 8; u++) {
        int idx = u * 256 + t;
        int J = idx >> 7, s = (idx >> 5) & 3, lane = idx & 31;
        int g = lane >> 2, tig = lane & 3;
        int k0 = kc * 32 + s * 8 + tig;
        int n  = J * 8 + g;
        dst[idx * 2]     = f2tf(W[(size_t)k0 * HH + n]);
        dst[idx * 2 + 1] = f2tf(W[(size_t)(k0 + 4) * HH + n]);
    }
}

// ---------------------------------------------------------------------------
// Kernel 1: QKV GEMM (R5 mainloop). GRID TRANSPOSED: (3, MM/128) so the three
// CTAs sharing one 128-row x-slice are wave-adjacent -> x read once from DRAM,
// twice from L2 (was 3x DRAM).
// ---------------------------------------------------------------------------
#define XST 36
#define XBUF (128*XST)     // 4608
#define WBUF 4096
#define QKV_SMEM (17408*4)
#define SP 132

__global__ __launch_bounds__(256, 2) void qkv_mma_kernel(
    const float* __restrict__ x,
    const float* __restrict__ bq, const float* __restrict__ bk,
    const float* __restrict__ bv)
{
    extern __shared__ float smq[];
    float* xsb[2] = { smq,           smq + XBUF };
    float* wsb[2] = { smq + 2*XBUF,  smq + 2*XBUF + WBUF };
    float* sp = smq;

    const int by = blockIdx.x;          // output selector (fast-varying!)
    const int bx = blockIdx.y;          // row-tile index
    const float* bias = (by == 0) ? bq : (by == 1) ? bk : bv;
    float* outg = (by == 0) ? g_q : (by == 1) ? g_k : g_v;
    const float* wp = g_wp + (size_t)by * (EE * HH);

    const int t    = threadIdx.x;
    const int w    = t >> 5;
    const int lane = t & 31;
    const int g    = lane >> 2;
    const int tig  = lane & 3;
    const int rg   = w & 3;
    const int cg   = w >> 2;
    const int m0   = bx * 128;

    float4 acc[2][8];
#pragma unroll
    for (int i = 0; i < 2; i++)
#pragma unroll
        for (int j = 0; j < 8; j++) acc[i][j] = make_float4(0.f, 0.f, 0.f, 0.f);

#define LOAD_CHUNK(KC, BUF) do {                                              \
        float* xd = xsb[BUF]; float* wd = wsb[BUF];                           \
        _Pragma("unroll")                                                     \
        for (int u = 0; u < 4; u++) {                                         \
            int idx = u * 256 + t;                                            \
            int row = idx >> 3, c4 = (idx & 7) * 4;                           \
            cpasync16(xd + row * XST + c4,                                    \
                      x + (size_t)(m0 + row) * EE + (KC) + c4);               \
        }                                                                     \
        _Pragma("unroll")                                                     \
        for (int u = 0; u < 4; u++) {                                         \
            int idx = u * 256 + t;                                            \
            cpasync16(wd + idx * 4, wp + ((KC) >> 5) * 4096 + idx * 4);       \
        }                                                                     \
        CP_COMMIT();                                                          \
    } while (0)

    LOAD_CHUNK(0, 0);

    for (int c = 0; c < 32; c++) {
        const int buf = c & 1;
        if (c < 31) { LOAD_CHUNK((c + 1) * 32, buf ^ 1); cp_wait<1>(); }
        else        { cp_wait<0>(); }
        __syncthreads();

        const float* xb = xsb[buf];
        const uint2* wb2 = (const uint2*)wsb[buf];
#pragma unroll
        for (int s = 0; s < 4; s++) {
            uint4 a[2];
#pragma unroll
            for (int i = 0; i < 2; i++) {
                const float* xr0 = xb + ((2*rg + i)*16 + g)     * XST + s*8 + tig;
                const float* xr1 = xb + ((2*rg + i)*16 + g + 8) * XST + s*8 + tig;
                a[i].x = f2tf(xr0[0]); a[i].y = f2tf(xr1[0]);
                a[i].z = f2tf(xr0[4]); a[i].w = f2tf(xr1[4]);
            }
#pragma unroll
            for (int j = 0; j < 8; j++) {
                uint2 bf = wb2[(((cg * 8 + j) * 4 + s) * 32) + lane];
                mma_tf32(acc[0][j], a[0], bf);
                mma_tf32(acc[1][j], a[1], bf);
            }
        }
        __syncthreads();
    }

    const float SCALE = 0.08838834764831845f;
    const float sc = (by == 0) ? SCALE : 1.0f;
#pragma unroll
    for (int i = 0; i < 2; i++) {
        int r0 = rg * 32 + i * 16 + g;
#pragma unroll
        for (int j = 0; j < 8; j++) {
            int c0 = cg * 64 + j * 8 + 2 * tig;
            float b0 = __ldg(bias + c0), b1 = __ldg(bias + c0 + 1);
            float4 a = acc[i][j];
            *(float2*)&sp[r0 * SP + c0]       = make_float2((a.x + b0) * sc, (a.y + b1) * sc);
            *(float2*)&sp[(r0 + 8) * SP + c0] = make_float2((a.z + b0) * sc, (a.w + b1) * sc);
        }
    }
    __syncthreads();

    if (by == 0) {
        unsigned* dst = (unsigned*)(outg + (size_t)bx * 16384);
#pragma unroll
        for (int i = 0; i < 16; i++) {
            float v0 = sp[(w * 16 + g)     * SP + 8 * i + tig];
            float v1 = sp[(w * 16 + g + 8) * SP + 8 * i + tig];
            float v2 = sp[(w * 16 + g)     * SP + 8 * i + tig + 4];
            float v3 = sp[(w * 16 + g + 8) * SP + 8 * i + tig + 4];
            *(uint4*)(dst + ((w * 16 + i) * 32 + lane) * 4) =
                make_uint4(f2tf(v0), f2tf(v1), f2tf(v2), f2tf(v3));
        }
    } else if (by == 1) {
        const int pg = (g >> 1) + ((g & 1) << 2);   // pi^-1(g)
#pragma unroll
        for (int it = 0; it < 32; it++) {
            int idx = w * 32 + it;
            int kt = idx >> 7, j = (idx >> 4) & 7, s = idx & 15;
            int row = kt * 64 + 8 * j + pg;
            float v0 = sp[row * SP + 8 * s + tig];
            float v1 = sp[row * SP + 8 * s + tig + 4];
            unsigned* dst = (unsigned*)(outg + (size_t)(2 * bx + kt) * 8192);
            *(uint2*)(dst + ((j * 16 + s) * 32 + lane) * 2) = make_uint2(f2tf(v0), f2tf(v1));
        }
    } else {
#pragma unroll
        for (int it = 0; it < 32; it++) {
            int idx = w * 32 + it;
            int kt = idx >> 7, ht = (idx >> 3) & 15, skv = idx & 7;
            float v0 = sp[(kt * 64 + 8 * skv + tig)     * SP + 8 * ht + g];
            float v1 = sp[(kt * 64 + 8 * skv + tig + 4) * SP + 8 * ht + g];
            unsigned* dst = (unsigned*)(outg + (size_t)(2 * bx + kt) * 8192);
            *(uint2*)(dst + ((ht * 8 + skv) * 32 + lane) * 2) = make_uint2(f2tf(v0), f2tf(v1));
        }
    }
}

// ---------------------------------------------------------------------------
// Kernel 2: flash attention — EXACT R5 version (best validated).
// Deferred-PV pipeline, Q in registers. K,V double-buffered.
// CTA = 128 q-rows, 256 threads, smem 128 KB, 1 CTA/SM.
// Grid 16 x 8; CTA does q-tiles (bx, 31-bx): 66 kv-iters each (balanced).
// ---------------------------------------------------------------------------
#define ATT_SMEM (32768 * 4)   // 131072 B

__global__ __launch_bounds__(256, 1) void attn_mma_kernel(float* __restrict__ out)
{
    extern __shared__ float sm[];
    unsigned* kbu[2] = { (unsigned*)sm,             (unsigned*)(sm + 8192) };
    unsigned* vbu[2] = { (unsigned*)(sm + 16384),   (unsigned*)(sm + 24576) };

    const int t    = threadIdx.x;
    const int w    = t >> 5;       // 0..7
    const int lane = t & 31;
    const int g    = lane >> 2;
    const int tig  = lane & 3;
    const int b    = blockIdx.y;
    const int bx   = blockIdx.x;   // 0..15

#pragma unroll 1
    for (int half = 0; half < 2; half++) {
        const int qt = half ? (31 - bx) : bx;   // 128-row q-tile

        // Q A-frags -> registers (rb = w)
        const unsigned* qg = (const unsigned*)(g_q + (size_t)(b * 32 + qt) * 16384);
        uint4 Q[16];
#pragma unroll
        for (int s = 0; s < 16; s++)
            Q[s] = *(const uint4*)(qg + ((w * 16 + s) * 32 + lane) * 4);

        float4 O[16];
#pragma unroll
        for (int ht = 0; ht < 16; ht++) O[ht] = make_float4(0.f, 0.f, 0.f, 0.f);
        float mrow[2] = {-3.0e38f, -3.0e38f};
        float lrow[2] = {0.f, 0.f};
        float aprev[2] = {1.f, 1.f};
        uint4 pa[8];

        const int ntiles = 2 * qt + 2;

        // prologue: K(0)
        {
            const float* kg = g_k + (size_t)(b * 64) * 8192;
#pragma unroll
            for (int u = 0; u < 8; u++) {
                int idx = u * 256 + t;
                cpasync16((float*)kbu[0] + idx * 4, kg + idx * 4);
            }
            CP_COMMIT();
        }

#pragma unroll 1
        for (int st = 0; st < ntiles; st++) {
            const int p = st & 1;

            cp_wait<0>();          // K(st) + V(st-1) complete
            __syncthreads();

            // issue V(st), K(st+1) — they fly during S + PV + softmax
            {
                const float* vg = g_v + (size_t)(b * 64 + st) * 8192;
#pragma unroll
                for (int u = 0; u < 8; u++) {
                    int idx = u * 256 + t;
                    cpasync16((float*)vbu[p] + idx * 4, vg + idx * 4);
                }
                CP_COMMIT();
            }
            if (st + 1 < ntiles) {
                const float* kg = g_k + (size_t)(b * 64 + st + 1) * 8192;
#pragma unroll
                for (int u = 0; u < 8; u++) {
                    int idx = u * 256 + t;
                    cpasync16((float*)kbu[p ^ 1] + idx * 4, kg + idx * 4);
                }
                CP_COMMIT();
            }

            // ---- S = Q @ K^T  (16 x 64 per warp) ----
            const unsigned* ksu = kbu[p];
            float4 sa[8];
#pragma unroll
            for (int j = 0; j < 8; j++) sa[j] = make_float4(0.f, 0.f, 0.f, 0.f);
#pragma unroll
            for (int s = 0; s < 16; s++) {
#pragma unroll
                for (int j = 0; j < 8; j++) {
                    uint2 bf = *(const uint2*)(ksu + ((j * 16 + s) * 32 + lane) * 2);
                    mma_tf32(sa[j], Q[s], bf);
                }
            }

            // ---- deferred: O *= alpha(st-1); O += P(st-1) @ V(st-1) ----
            if (st > 0) {
#pragma unroll
                for (int ht = 0; ht < 16; ht++) {
                    O[ht].x *= aprev[0]; O[ht].y *= aprev[0];
                    O[ht].z *= aprev[1]; O[ht].w *= aprev[1];
                }
                const unsigned* vsu = vbu[p ^ 1];
#pragma unroll
                for (int skv = 0; skv < 8; skv++) {
#pragma unroll
                    for (int ht = 0; ht < 16; ht++) {
                        uint2 bf = *(const uint2*)(vsu + ((ht * 8 + skv) * 32 + lane) * 2);
                        mma_tf32(O[ht], pa[skv], bf);
                    }
                }
            }

            // ---- causal mask (x<->kv 8j+tig, y<->8j+tig+4, permuted K) ----
            if (st >= 2 * qt) {
                const int rbase = qt * 128 + w * 16 + g;
#pragma unroll
                for (int j = 0; j < 8; j++) {
                    int kvx = st * 64 + 8 * j + tig;
                    if (kvx     > rbase)     sa[j].x = -1.0e30f;
                    if (kvx + 4 > rbase)     sa[j].y = -1.0e30f;
                    if (kvx     > rbase + 8) sa[j].z = -1.0e30f;
                    if (kvx + 4 > rbase + 8) sa[j].w = -1.0e30f;
                }
            }

            // ---- softmax(st): stats + exp + pack pa (no O touch) ----
#pragma unroll
            for (int h = 0; h < 2; h++) {
                float lm = -3.0e38f;
#pragma unroll
                for (int j = 0; j < 8; j++) {
                    float v0 = h ? sa[j].z : sa[j].x;
                    float v1 = h ? sa[j].w : sa[j].y;
                    lm = fmaxf(lm, fmaxf(v0, v1));
                }
                lm = fmaxf(lm, __shfl_xor_sync(0xffffffffu, lm, 1));
                lm = fmaxf(lm, __shfl_xor_sync(0xffffffffu, lm, 2));
                float mn = fmaxf(mrow[h], lm);
                aprev[h] = __expf(mrow[h] - mn);
                mrow[h] = mn;
                float ls = 0.f;
#pragma unroll
                for (int j = 0; j < 8; j++) {
                    float v0 = h ? sa[j].z : sa[j].x;
                    float v1 = h ? sa[j].w : sa[j].y;
                    v0 = __expf(v0 - mn);
                    v1 = __expf(v1 - mn);
                    if (h) { sa[j].z = v0; sa[j].w = v1; }
                    else   { sa[j].x = v0; sa[j].y = v1; }
                    ls += v0 + v1;
                }
                ls += __shfl_xor_sync(0xffffffffu, ls, 1);
                ls += __shfl_xor_sync(0xffffffffu, ls, 2);
                lrow[h] = lrow[h] * aprev[h] + ls;
            }
#pragma unroll
            for (int j = 0; j < 8; j++)
                pa[j] = make_uint4(f2tf(sa[j].x), f2tf(sa[j].z),
                                   f2tf(sa[j].y), f2tf(sa[j].w));
        }

        // ---- epilogue: final deferred PV, then normalize + store ----
        cp_wait<0>();
        __syncthreads();
        {
#pragma unroll
            for (int ht = 0; ht < 16; ht++) {
                O[ht].x *= aprev[0]; O[ht].y *= aprev[0];
                O[ht].z *= aprev[1]; O[ht].w *= aprev[1];
            }
            const unsigned* vsu = vbu[(ntiles - 1) & 1];
#pragma unroll
            for (int skv = 0; skv < 8; skv++) {
#pragma unroll
                for (int ht = 0; ht < 16; ht++) {
                    uint2 bf = *(const uint2*)(vsu + ((ht * 8 + skv) * 32 + lane) * 2);
                    mma_tf32(O[ht], pa[skv], bf);
                }
            }
        }
        __syncthreads();   // buffers reusable next half

        const float inv0 = 1.0f / lrow[0];
        const float inv1 = 1.0f / lrow[1];
        const int r0 = qt * 128 + w * 16 + g;
        float* o0 = out + ((size_t)b * TT + r0) * HH;
        float* o1 = o0 + 8 * HH;
#pragma unroll
        for (int ht = 0; ht < 16; ht++) {
            int col = ht * 8 + 2 * tig;
            *(float2*)(o0 + col) = make_float2(O[ht].x * inv0, O[ht].y * inv0);
            *(float2*)(o1 + col) = make_float2(O[ht].z * inv1, O[ht].w * inv1);
        }
    }
}

// ---------------------------------------------------------------------------
extern "C" void kernel_launch(void* const* d_in, const int* in_sizes, int n_in,
                              void* d_out, int out_size)
{
    const float* x  = (const float*)d_in[0];
    const float* Wq = (const float*)d_in[1];
    const float* bq = (const float*)d_in[2];
    const float* Wk = (const float*)d_in[3];
    const float* bk = (const float*)d_in[4];
    const float* Wv = (const float*)d_in[5];
    const float* bv = (const float*)d_in[6];
    float* out = (float*)d_out;

    cudaFuncSetAttribute(qkv_mma_kernel,
                         cudaFuncAttributeMaxDynamicSharedMemorySize, QKV_SMEM);
    cudaFuncSetAttribute(attn_mma_kernel,
                         cudaFuncAttributeMaxDynamicSharedMemorySize, ATT_SMEM);

    wpack_kernel<<<dim3(32, 3), 256>>>(Wq, Wk, Wv);
    qkv_mma_kernel<<<dim3(3, MM / 128), 256, QKV_SMEM>>>(x, bq, bk, bv);
    attn_mma_kernel<<<dim3(16, BB), 256, ATT_SMEM>>>(out);
}

// round 11
// speedup vs baseline: 1.5483x; 1.5483x over previous
#include <cuda_runtime.h>
#include <cstdint>

#define BB 8
#define TT 4096
#define EE 1024
#define HH 128
#define MM (BB*TT)

// ---------------------------------------------------------------------------
// Scratch (tf32, pre-packed into mma.sync fragment order):
// g_q: per 128-row tile: [rb*16+s][lane][4 words]  (A-frags)
// g_k: per 64-row kv tile: [j*16+s][lane][2 words] (B-frags, kv cols permuted
//      pi(c)=2c / 2(c-4)+1 so the S C-layout equals the PV A-frag order)
// g_v: per 64-row kv tile: [ht*8+skv][lane][2 words]
// g_wp: W B-frags: [by][kc 0..31][J 0..15][s 0..3][lane][2 words]
// ---------------------------------------------------------------------------
static __device__ __align__(16) float g_q[(size_t)MM * HH];
static __device__ __align__(16) float g_k[(size_t)MM * HH];
static __device__ __align__(16) float g_v[(size_t)MM * HH];
static __device__ __align__(16) float g_wp[3u * EE * HH];

__device__ __forceinline__ unsigned f2tf(float f) {
    unsigned u;
    asm("cvt.rna.tf32.f32 %0, %1;" : "=r"(u) : "f"(f));
    return u;
}

__device__ __forceinline__ void mma_tf32(float4& d, const uint4& a, const uint2& b) {
    asm volatile(
        "mma.sync.aligned.m16n8k8.row.col.f32.tf32.tf32.f32 "
        "{%0,%1,%2,%3}, {%4,%5,%6,%7}, {%8,%9}, {%0,%1,%2,%3};"
        : "+f"(d.x), "+f"(d.y), "+f"(d.z), "+f"(d.w)
        : "r"(a.x), "r"(a.y), "r"(a.z), "r"(a.w), "r"(b.x), "r"(b.y));
}

__device__ __forceinline__ void cpasync16(void* sdst, const void* gsrc) {
    unsigned s = (unsigned)__cvta_generic_to_shared(sdst);
    asm volatile("cp.async.cg.shared.global [%0], [%1], 16;" :: "r"(s), "l"(gsrc));
}
#define CP_COMMIT() asm volatile("cp.async.commit_group;")
template <int N> __device__ __forceinline__ void cp_wait() {
    asm volatile("cp.async.wait_group %0;" :: "n"(N));
}

// ---------------------------------------------------------------------------
// Kernel 0: one-shot W pre-pack into B-frag tf32 layout.
// ---------------------------------------------------------------------------
__global__ __launch_bounds__(256) void wpack_kernel(
    const float* __restrict__ Wq, const float* __restrict__ Wk,
    const float* __restrict__ Wv)
{
    const int kc = blockIdx.x;
    const int by = blockIdx.y;
    const float* W = (by == 0) ? Wq : (by == 1) ? Wk : Wv;
    unsigned* dst = (unsigned*)(g_wp + (size_t)by * (EE * HH) + kc * 4096);
    const int t = threadIdx.x;
#pragma unroll
    for (int u = 0; u < 8; u++) {
        int idx = u * 256 + t;
        int J = idx >> 7, s = (idx >> 5) & 3, lane = idx & 31;
        int g = lane >> 2, tig = lane & 3;
        int k0 = kc * 32 + s * 8 + tig;
        int n  = J * 8 + g;
        dst[idx * 2]     = f2tf(W[(size_t)k0 * HH + n]);
        dst[idx * 2 + 1] = f2tf(W[(size_t)(k0 + 4) * HH + n]);
    }
}

// ---------------------------------------------------------------------------
// Kernel 1: QKV GEMM (R5 mainloop). GRID TRANSPOSED: (3, MM/128) so the three
// CTAs sharing one 128-row x-slice are wave-adjacent -> x read once from DRAM,
// twice from L2 (was 3x DRAM).
// ---------------------------------------------------------------------------
#define XST 36
#define XBUF (128*XST)     // 4608
#define WBUF 4096
#define QKV_SMEM (17408*4)
#define SP 132

__global__ __launch_bounds__(256, 2) void qkv_mma_kernel(
    const float* __restrict__ x,
    const float* __restrict__ bq, const float* __restrict__ bk,
    const float* __restrict__ bv)
{
    extern __shared__ float smq[];
    float* xsb[2] = { smq,           smq + XBUF };
    float* wsb[2] = { smq + 2*XBUF,  smq + 2*XBUF + WBUF };
    float* sp = smq;

    const int by = blockIdx.x;          // output selector (fast-varying!)
    const int bx = blockIdx.y;          // row-tile index
    const float* bias = (by == 0) ? bq : (by == 1) ? bk : bv;
    float* outg = (by == 0) ? g_q : (by == 1) ? g_k : g_v;
    const float* wp = g_wp + (size_t)by * (EE * HH);

    const int t    = threadIdx.x;
    const int w    = t >> 5;
    const int lane = t & 31;
    const int g    = lane >> 2;
    const int tig  = lane & 3;
    const int rg   = w & 3;
    const int cg   = w >> 2;
    const int m0   = bx * 128;

    float4 acc[2][8];
#pragma unroll
    for (int i = 0; i < 2; i++)
#pragma unroll
        for (int j = 0; j < 8; j++) acc[i][j] = make_float4(0.f, 0.f, 0.f, 0.f);

#define LOAD_CHUNK(KC, BUF) do {                                              \
        float* xd = xsb[BUF]; float* wd = wsb[BUF];                           \
        _Pragma("unroll")                                                     \
        for (int u = 0; u < 4; u++) {                                         \
            int idx = u * 256 + t;                                            \
            int row = idx >> 3, c4 = (idx & 7) * 4;                           \
            cpasync16(xd + row * XST + c4,                                    \
                      x + (size_t)(m0 + row) * EE + (KC) + c4);               \
        }                                                                     \
        _Pragma("unroll")                                                     \
        for (int u = 0; u < 4; u++) {                                         \
            int idx = u * 256 + t;                                            \
            cpasync16(wd + idx * 4, wp + ((KC) >> 5) * 4096 + idx * 4);       \
        }                                                                     \
        CP_COMMIT();                                                          \
    } while (0)

    LOAD_CHUNK(0, 0);

    for (int c = 0; c < 32; c++) {
        const int buf = c & 1;
        if (c < 31) { LOAD_CHUNK((c + 1) * 32, buf ^ 1); cp_wait<1>(); }
        else        { cp_wait<0>(); }
        __syncthreads();

        const float* xb = xsb[buf];
        const uint2* wb2 = (const uint2*)wsb[buf];
#pragma unroll
        for (int s = 0; s < 4; s++) {
            uint4 a[2];
#pragma unroll
            for (int i = 0; i < 2; i++) {
                const float* xr0 = xb + ((2*rg + i)*16 + g)     * XST + s*8 + tig;
                const float* xr1 = xb + ((2*rg + i)*16 + g + 8) * XST + s*8 + tig;
                a[i].x = f2tf(xr0[0]); a[i].y = f2tf(xr1[0]);
                a[i].z = f2tf(xr0[4]); a[i].w = f2tf(xr1[4]);
            }
#pragma unroll
            for (int j = 0; j < 8; j++) {
                uint2 bf = wb2[(((cg * 8 + j) * 4 + s) * 32) + lane];
                mma_tf32(acc[0][j], a[0], bf);
                mma_tf32(acc[1][j], a[1], bf);
            }
        }
        __syncthreads();
    }

    const float SCALE = 0.08838834764831845f;
    const float sc = (by == 0) ? SCALE : 1.0f;
#pragma unroll
    for (int i = 0; i < 2; i++) {
        int r0 = rg * 32 + i * 16 + g;
#pragma unroll
        for (int j = 0; j < 8; j++) {
            int c0 = cg * 64 + j * 8 + 2 * tig;
            float b0 = __ldg(bias + c0), b1 = __ldg(bias + c0 + 1);
            float4 a = acc[i][j];
            *(float2*)&sp[r0 * SP + c0]       = make_float2((a.x + b0) * sc, (a.y + b1) * sc);
            *(float2*)&sp[(r0 + 8) * SP + c0] = make_float2((a.z + b0) * sc, (a.w + b1) * sc);
        }
    }
    __syncthreads();

    if (by == 0) {
        unsigned* dst = (unsigned*)(outg + (size_t)bx * 16384);
#pragma unroll
        for (int i = 0; i < 16; i++) {
            float v0 = sp[(w * 16 + g)     * SP + 8 * i + tig];
            float v1 = sp[(w * 16 + g + 8) * SP + 8 * i + tig];
            float v2 = sp[(w * 16 + g)     * SP + 8 * i + tig + 4];
            float v3 = sp[(w * 16 + g + 8) * SP + 8 * i + tig + 4];
            *(uint4*)(dst + ((w * 16 + i) * 32 + lane) * 4) =
                make_uint4(f2tf(v0), f2tf(v1), f2tf(v2), f2tf(v3));
        }
    } else if (by == 1) {
        const int pg = (g >> 1) + ((g & 1) << 2);   // pi^-1(g)
#pragma unroll
        for (int it = 0; it < 32; it++) {
            int idx = w * 32 + it;
            int kt = idx >> 7, j = (idx >> 4) & 7, s = idx & 15;
            int row = kt * 64 + 8 * j + pg;
            float v0 = sp[row * SP + 8 * s + tig];
            float v1 = sp[row * SP + 8 * s + tig + 4];
            unsigned* dst = (unsigned*)(outg + (size_t)(2 * bx + kt) * 8192);
            *(uint2*)(dst + ((j * 16 + s) * 32 + lane) * 2) = make_uint2(f2tf(v0), f2tf(v1));
        }
    } else {
#pragma unroll
        for (int it = 0; it < 32; it++) {
            int idx = w * 32 + it;
            int kt = idx >> 7, ht = (idx >> 3) & 15, skv = idx & 7;
            float v0 = sp[(kt * 64 + 8 * skv + tig)     * SP + 8 * ht + g];
            float v1 = sp[(kt * 64 + 8 * skv + tig + 4) * SP + 8 * ht + g];
            unsigned* dst = (unsigned*)(outg + (size_t)(2 * bx + kt) * 8192);
            *(uint2*)(dst + ((ht * 8 + skv) * 32 + lane) * 2) = make_uint2(f2tf(v0), f2tf(v1));
        }
    }
}

// ---------------------------------------------------------------------------
// Kernel 2: flash attention — EXACT R5 version (best validated).
// Deferred-PV pipeline, Q in registers. K,V double-buffered.
// CTA = 128 q-rows, 256 threads, smem 128 KB, 1 CTA/SM.
// Grid 16 x 8; CTA does q-tiles (bx, 31-bx): 66 kv-iters each (balanced).
// ---------------------------------------------------------------------------
#define ATT_SMEM (32768 * 4)   // 131072 B

__global__ __launch_bounds__(256, 1) void attn_mma_kernel(float* __restrict__ out)
{
    extern __shared__ float sm[];
    unsigned* kbu[2] = { (unsigned*)sm,             (unsigned*)(sm + 8192) };
    unsigned* vbu[2] = { (unsigned*)(sm + 16384),   (unsigned*)(sm + 24576) };

    const int t    = threadIdx.x;
    const int w    = t >> 5;       // 0..7
    const int lane = t & 31;
    const int g    = lane >> 2;
    const int tig  = lane & 3;
    const int b    = blockIdx.y;
    const int bx   = blockIdx.x;   // 0..15

#pragma unroll 1
    for (int half = 0; half < 2; half++) {
        const int qt = half ? (31 - bx) : bx;   // 128-row q-tile

        // Q A-frags -> registers (rb = w)
        const unsigned* qg = (const unsigned*)(g_q + (size_t)(b * 32 + qt) * 16384);
        uint4 Q[16];
#pragma unroll
        for (int s = 0; s < 16; s++)
            Q[s] = *(const uint4*)(qg + ((w * 16 + s) * 32 + lane) * 4);

        float4 O[16];
#pragma unroll
        for (int ht = 0; ht < 16; ht++) O[ht] = make_float4(0.f, 0.f, 0.f, 0.f);
        float mrow[2] = {-3.0e38f, -3.0e38f};
        float lrow[2] = {0.f, 0.f};
        float aprev[2] = {1.f, 1.f};
        uint4 pa[8];

        const int ntiles = 2 * qt + 2;

        // prologue: K(0)
        {
            const float* kg = g_k + (size_t)(b * 64) * 8192;
#pragma unroll
            for (int u = 0; u < 8; u++) {
                int idx = u * 256 + t;
                cpasync16((float*)kbu[0] + idx * 4, kg + idx * 4);
            }
            CP_COMMIT();
        }

#pragma unroll 1
        for (int st = 0; st < ntiles; st++) {
            const int p = st & 1;

            cp_wait<0>();          // K(st) + V(st-1) complete
            __syncthreads();

            // issue V(st), K(st+1) — they fly during S + PV + softmax
            {
                const float* vg = g_v + (size_t)(b * 64 + st) * 8192;
#pragma unroll
                for (int u = 0; u < 8; u++) {
                    int idx = u * 256 + t;
                    cpasync16((float*)vbu[p] + idx * 4, vg + idx * 4);
                }
                CP_COMMIT();
            }
            if (st + 1 < ntiles) {
                const float* kg = g_k + (size_t)(b * 64 + st + 1) * 8192;
#pragma unroll
                for (int u = 0; u < 8; u++) {
                    int idx = u * 256 + t;
                    cpasync16((float*)kbu[p ^ 1] + idx * 4, kg + idx * 4);
                }
                CP_COMMIT();
            }

            // ---- S = Q @ K^T  (16 x 64 per warp) ----
            const unsigned* ksu = kbu[p];
            float4 sa[8];
#pragma unroll
            for (int j = 0; j < 8; j++) sa[j] = make_float4(0.f, 0.f, 0.f, 0.f);
#pragma unroll
            for (int s = 0; s < 16; s++) {
#pragma unroll
                for (int j = 0; j < 8; j++) {
                    uint2 bf = *(const uint2*)(ksu + ((j * 16 + s) * 32 + lane) * 2);
                    mma_tf32(sa[j], Q[s], bf);
                }
            }

            // ---- deferred: O *= alpha(st-1); O += P(st-1) @ V(st-1) ----
            if (st > 0) {
#pragma unroll
                for (int ht = 0; ht < 16; ht++) {
                    O[ht].x *= aprev[0]; O[ht].y *= aprev[0];
                    O[ht].z *= aprev[1]; O[ht].w *= aprev[1];
                }
                const unsigned* vsu = vbu[p ^ 1];
#pragma unroll
                for (int skv = 0; skv < 8; skv++) {
#pragma unroll
                    for (int ht = 0; ht < 16; ht++) {
                        uint2 bf = *(const uint2*)(vsu + ((ht * 8 + skv) * 32 + lane) * 2);
                        mma_tf32(O[ht], pa[skv], bf);
                    }
                }
            }

            // ---- causal mask (x<->kv 8j+tig, y<->8j+tig+4, permuted K) ----
            if (st >= 2 * qt) {
                const int rbase = qt * 128 + w * 16 + g;
#pragma unroll
                for (int j = 0; j < 8; j++) {
                    int kvx = st * 64 + 8 * j + tig;
                    if (kvx     > rbase)     sa[j].x = -1.0e30f;
                    if (kvx + 4 > rbase)     sa[j].y = -1.0e30f;
                    if (kvx     > rbase + 8) sa[j].z = -1.0e30f;
                    if (kvx + 4 > rbase + 8) sa[j].w = -1.0e30f;
                }
            }

            // ---- softmax(st): stats + exp + pack pa (no O touch) ----
#pragma unroll
            for (int h = 0; h < 2; h++) {
                float lm = -3.0e38f;
#pragma unroll
                for (int j = 0; j < 8; j++) {
                    float v0 = h ? sa[j].z : sa[j].x;
                    float v1 = h ? sa[j].w : sa[j].y;
                    lm = fmaxf(lm, fmaxf(v0, v1));
                }
                lm = fmaxf(lm, __shfl_xor_sync(0xffffffffu, lm, 1));
                lm = fmaxf(lm, __shfl_xor_sync(0xffffffffu, lm, 2));
                float mn = fmaxf(mrow[h], lm);
                aprev[h] = __expf(mrow[h] - mn);
                mrow[h] = mn;
                float ls = 0.f;
#pragma unroll
                for (int j = 0; j < 8; j++) {
                    float v0 = h ? sa[j].z : sa[j].x;
                    float v1 = h ? sa[j].w : sa[j].y;
                    v0 = __expf(v0 - mn);
                    v1 = __expf(v1 - mn);
                    if (h) { sa[j].z = v0; sa[j].w = v1; }
                    else   { sa[j].x = v0; sa[j].y = v1; }
                    ls += v0 + v1;
                }
                ls += __shfl_xor_sync(0xffffffffu, ls, 1);
                ls += __shfl_xor_sync(0xffffffffu, ls, 2);
                lrow[h] = lrow[h] * aprev[h] + ls;
            }
#pragma unroll
            for (int j = 0; j < 8; j++)
                pa[j] = make_uint4(f2tf(sa[j].x), f2tf(sa[j].z),
                                   f2tf(sa[j].y), f2tf(sa[j].w));
        }

        // ---- epilogue: final deferred PV, then normalize + store ----
        cp_wait<0>();
        __syncthreads();
        {
#pragma unroll
            for (int ht = 0; ht < 16; ht++) {
                O[ht].x *= aprev[0]; O[ht].y *= aprev[0];
                O[ht].z *= aprev[1]; O[ht].w *= aprev[1];
            }
            const unsigned* vsu = vbu[(ntiles - 1) & 1];
#pragma unroll
            for (int skv = 0; skv < 8; skv++) {
#pragma unroll
                for (int ht = 0; ht < 16; ht++) {
                    uint2 bf = *(const uint2*)(vsu + ((ht * 8 + skv) * 32 + lane) * 2);
                    mma_tf32(O[ht], pa[skv], bf);
                }
            }
        }
        __syncthreads();   // buffers reusable next half

        const float inv0 = 1.0f / lrow[0];
        const float inv1 = 1.0f / lrow[1];
        const int r0 = qt * 128 + w * 16 + g;
        float* o0 = out + ((size_t)b * TT + r0) * HH;
        float* o1 = o0 + 8 * HH;
#pragma unroll
        for (int ht = 0; ht < 16; ht++) {
            int col = ht * 8 + 2 * tig;
            *(float2*)(o0 + col) = make_float2(O[ht].x * inv0, O[ht].y * inv0);
            *(float2*)(o1 + col) = make_float2(O[ht].z * inv1, O[ht].w * inv1);
        }
    }
}

// ---------------------------------------------------------------------------
extern "C" void kernel_launch(void* const* d_in, const int* in_sizes, int n_in,
                              void* d_out, int out_size)
{
    const float* x  = (const float*)d_in[0];
    const float* Wq = (const float*)d_in[1];
    const float* bq = (const float*)d_in[2];
    const float* Wk = (const float*)d_in[3];
    const float* bk = (const float*)d_in[4];
    const float* Wv = (const float*)d_in[5];
    const float* bv = (const float*)d_in[6];
    float* out = (float*)d_out;

    cudaFuncSetAttribute(qkv_mma_kernel,
                         cudaFuncAttributeMaxDynamicSharedMemorySize, QKV_SMEM);
    cudaFuncSetAttribute(attn_mma_kernel,
                         cudaFuncAttributeMaxDynamicSharedMemorySize, ATT_SMEM);

    wpack_kernel<<<dim3(32, 3), 256>>>(Wq, Wk, Wv);
    qkv_mma_kernel<<<dim3(3, MM / 128), 256, QKV_SMEM>>>(x, bq, bk, bv);
    attn_mma_kernel<<<dim3(16, BB), 256, ATT_SMEM>>>(out);
}

// round 13
// speedup vs baseline: 2.1890x; 1.4138x over previous
#include <cuda_runtime.h>
#include <cuda_fp16.h>
#include <cstdint>

#define BB 8
#define TT 4096
#define EE 1024
#define HH 128
#define MM (BB*TT)

// ---------------------------------------------------------------------------
// Scratch (fp16, pre-packed into m16n8k16 fragment order):
// g_qh: per 128-row tile: [rb*8+s][lane][uint4]   (A-frags, s = k16 step)
// g_kh: per 64-kv tile:   [j*8+s][lane][uint2]    (B-frags for S = Q K^T)
// g_vh: per 64-kv tile:   [ht*4+kc][lane][uint2]  (B-frags for O = P V)
// g_wh: W B-frags: [o][kc 0..31][(j*2+s) 0..31][lane][uint2]
// ---------------------------------------------------------------------------
static __device__ __align__(16) unsigned g_qh[(size_t)MM * HH / 2];
static __device__ __align__(16) unsigned g_kh[(size_t)MM * HH / 2];
static __device__ __align__(16) unsigned g_vh[(size_t)MM * HH / 2];
static __device__ __align__(16) unsigned g_wh[3u * EE * HH / 2];

__device__ __forceinline__ unsigned h2pack(float lo, float hi) {
    __half2 h = __floats2half2_rn(lo, hi);   // .x = lo (low 16 bits)
    return *(unsigned*)&h;
}

// m16n8k16 fp16 mma, f32 accumulate
__device__ __forceinline__ void mma_f16(float4& d, const uint4& a, const uint2& b) {
    asm volatile(
        "mma.sync.aligned.m16n8k16.row.col.f32.f16.f16.f32 "
        "{%0,%1,%2,%3}, {%4,%5,%6,%7}, {%8,%9}, {%0,%1,%2,%3};"
        : "+f"(d.x), "+f"(d.y), "+f"(d.z), "+f"(d.w)
        : "r"(a.x), "r"(a.y), "r"(a.z), "r"(a.w), "r"(b.x), "r"(b.y));
}

__device__ __forceinline__ void cpasync16(void* sdst, const void* gsrc) {
    unsigned s = (unsigned)__cvta_generic_to_shared(sdst);
    asm volatile("cp.async.cg.shared.global [%0], [%1], 16;" :: "r"(s), "l"(gsrc));
}
#define CP_COMMIT() asm volatile("cp.async.commit_group;")
template <int N> __device__ __forceinline__ void cp_wait() {
    asm volatile("cp.async.wait_group %0;" :: "n"(N));
}

// ---------------------------------------------------------------------------
// Kernel 0: one-shot W pre-pack into fp16 B-frag layout. grid (32, 3).
// word0 = {W[k0][n], W[k0+1][n]}, word1 = {W[k0+8][n], W[k0+9][n]},
// k0 = kc*32 + 16s + 2tig, n = 8j + g.
// ---------------------------------------------------------------------------
__global__ __launch_bounds__(256) void wpack_kernel(
    const float* __restrict__ Wq, const float* __restrict__ Wk,
    const float* __restrict__ Wv)
{
    const int kc = blockIdx.x;
    const int o  = blockIdx.y;
    const float* W = (o == 0) ? Wq : (o == 1) ? Wk : Wv;
    unsigned* dst = g_wh + ((size_t)o * 32 + kc) * 2048;
    const int t = threadIdx.x;
#pragma unroll
    for (int u = 0; u < 4; u++) {
        int idx = u * 256 + t;            // 0..1023 = js*32 + lane
        int js = idx >> 5, lane = idx & 31;
        int j = js >> 1, s = js & 1;
        int g = lane >> 2, tig = lane & 3;
        int n  = 8 * j + g;
        int k0 = kc * 32 + 16 * s + 2 * tig;
        dst[idx * 2]     = h2pack(W[(size_t)k0 * HH + n],       W[(size_t)(k0 + 1) * HH + n]);
        dst[idx * 2 + 1] = h2pack(W[(size_t)(k0 + 8) * HH + n], W[(size_t)(k0 + 9) * HH + n]);
    }
}

// ---------------------------------------------------------------------------
// Kernel 1: QKV GEMM, fp16 m16n8k16. R5 structure: 256 thr, grid (3, MM/128)
// (output-major for x L2 reuse). x fp32 in padded smem (LDS.64 pair + cvt),
// W fp16 frags via cp.async. 32 mma / chunk / warp (was 64).
// smem: xs[2] 128x36 f32 + wh[2] 2048 w = 13312 f; epilogue sp 128x132.
// ---------------------------------------------------------------------------
#define XST 36
#define XBUF (128*XST)     // 4608 floats
#define QKV_SMEM (16896*4) // sp dominates
#define SP 132

__global__ __launch_bounds__(256, 2) void qkv_mma_kernel(
    const float* __restrict__ x,
    const float* __restrict__ bq, const float* __restrict__ bk,
    const float* __restrict__ bv)
{
    extern __shared__ float smq[];
    float* xsb[2] = { smq, smq + XBUF };
    unsigned* whb[2] = { (unsigned*)(smq + 2*XBUF), (unsigned*)(smq + 2*XBUF) + 2048 };
    float* sp = smq;

    const int by = blockIdx.x;          // output selector (fast-varying)
    const int bx = blockIdx.y;          // 128-row tile
    const float* bias = (by == 0) ? bq : (by == 1) ? bk : bv;
    const unsigned* wp = g_wh + (size_t)by * 32 * 2048;

    const int t    = threadIdx.x;
    const int w    = t >> 5;
    const int lane = t & 31;
    const int g    = lane >> 2;
    const int tig  = lane & 3;
    const int rg   = w & 3;
    const int cg   = w >> 2;
    const int m0   = bx * 128;

    float4 acc[2][8];
#pragma unroll
    for (int i = 0; i < 2; i++)
#pragma unroll
        for (int j = 0; j < 8; j++) acc[i][j] = make_float4(0.f, 0.f, 0.f, 0.f);

#define LOAD_CHUNK(KC, BUF) do {                                              \
        float* xd = xsb[BUF]; unsigned* wd = whb[BUF];                        \
        _Pragma("unroll")                                                     \
        for (int u = 0; u < 4; u++) {                                         \
            int idx = u * 256 + t;                                            \
            int row = idx >> 3, c4 = (idx & 7) * 4;                           \
            cpasync16(xd + row * XST + c4,                                    \
                      x + (size_t)(m0 + row) * EE + (KC) + c4);               \
        }                                                                     \
        _Pragma("unroll")                                                     \
        for (int u = 0; u < 2; u++) {                                         \
            int idx = u * 256 + t;                                            \
            cpasync16(wd + idx * 4, wp + ((KC) >> 5) * 2048 + idx * 4);       \
        }                                                                     \
        CP_COMMIT();                                                          \
    } while (0)

    LOAD_CHUNK(0, 0);

    for (int c = 0; c < 32; c++) {
        const int buf = c & 1;
        if (c < 31) { LOAD_CHUNK((c + 1) * 32, buf ^ 1); cp_wait<1>(); }
        else        { cp_wait<0>(); }
        __syncthreads();

        const float* xb = xsb[buf];
        const uint2* wb2 = (const uint2*)whb[buf];
#pragma unroll
        for (int s = 0; s < 2; s++) {
            const int k0 = 16 * s;
            uint4 a[2];
#pragma unroll
            for (int i = 0; i < 2; i++) {
                const float* r0 = xb + ((2*rg + i)*16 + g)     * XST;
                const float* r1 = xb + ((2*rg + i)*16 + g + 8) * XST;
                float2 v0 = *(const float2*)(r0 + k0 + 2*tig);
                float2 v1 = *(const float2*)(r1 + k0 + 2*tig);
                float2 v2 = *(const float2*)(r0 + k0 + 8 + 2*tig);
                float2 v3 = *(const float2*)(r1 + k0 + 8 + 2*tig);
                a[i].x = h2pack(v0.x, v0.y);
                a[i].y = h2pack(v1.x, v1.y);
                a[i].z = h2pack(v2.x, v2.y);
                a[i].w = h2pack(v3.x, v3.y);
            }
#pragma unroll
            for (int j = 0; j < 8; j++) {
                uint2 bf = wb2[(((cg * 8 + j) * 2 + s) * 32) + lane];
                mma_f16(acc[0][j], a[0], bf);
                mma_f16(acc[1][j], a[1], bf);
            }
        }
        __syncthreads();
    }

    // ---- epilogue: bias (+q scale) -> fp32 smem ----
    const float SCALE = 0.08838834764831845f;
    const float sc = (by == 0) ? SCALE : 1.0f;
#pragma unroll
    for (int i = 0; i < 2; i++) {
        int r0 = rg * 32 + i * 16 + g;
#pragma unroll
        for (int j = 0; j < 8; j++) {
            int c0 = cg * 64 + j * 8 + 2 * tig;
            float b0 = __ldg(bias + c0), b1 = __ldg(bias + c0 + 1);
            float4 a = acc[i][j];
            *(float2*)&sp[r0 * SP + c0]       = make_float2((a.x + b0) * sc, (a.y + b1) * sc);
            *(float2*)&sp[(r0 + 8) * SP + c0] = make_float2((a.z + b0) * sc, (a.w + b1) * sc);
        }
    }
    __syncthreads();

    // ---- pack to fp16 fragment layouts ----
    if (by == 0) {
        unsigned* dst = g_qh + (size_t)bx * 8192;
#pragma unroll
        for (int s = 0; s < 8; s++) {
            const float* r0 = sp + (w * 16 + g) * SP;
            const float* r1 = sp + (w * 16 + g + 8) * SP;
            uint4 o;
            o.x = h2pack(r0[16*s + 2*tig],     r0[16*s + 2*tig + 1]);
            o.y = h2pack(r1[16*s + 2*tig],     r1[16*s + 2*tig + 1]);
            o.z = h2pack(r0[16*s + 8 + 2*tig], r0[16*s + 8 + 2*tig + 1]);
            o.w = h2pack(r1[16*s + 8 + 2*tig], r1[16*s + 8 + 2*tig + 1]);
            *(uint4*)(dst + ((w * 8 + s) * 32 + lane) * 4) = o;
        }
    } else if (by == 1) {
#pragma unroll
        for (int it = 0; it < 16; it++) {
            int idx = w * 16 + it;            // 0..127
            int kt = idx >> 6, j = (idx >> 3) & 7, s = idx & 7;
            const float* r = sp + (kt * 64 + 8 * j + g) * SP;
            unsigned* dst = g_kh + (size_t)(2 * bx + kt) * 4096;
            unsigned w0 = h2pack(r[16*s + 2*tig],     r[16*s + 2*tig + 1]);
            unsigned w1 = h2pack(r[16*s + 8 + 2*tig], r[16*s + 8 + 2*tig + 1]);
            *(uint2*)(dst + ((j * 8 + s) * 32 + lane) * 2) = make_uint2(w0, w1);
        }
    } else {
#pragma unroll
        for (int it = 0; it < 16; it++) {
            int idx = w * 16 + it;            // 0..127
            int kt = idx >> 6, ht = (idx >> 2) & 15, kc = idx & 3;
            int n = 8 * ht + g;
            int r0 = kt * 64 + 16 * kc + 2 * tig;
            unsigned* dst = g_vh + (size_t)(2 * bx + kt) * 4096;
            unsigned w0 = h2pack(sp[r0 * SP + n],       sp[(r0 + 1) * SP + n]);
            unsigned w1 = h2pack(sp[(r0 + 8) * SP + n], sp[(r0 + 9) * SP + n]);
            *(uint2*)(dst + ((ht * 4 + kc) * 32 + lane) * 2) = make_uint2(w0, w1);
        }
    }
}

// ---------------------------------------------------------------------------
// Kernel 2: flash attention, fp16 m16n8k16. R5/R11 structure: deferred-PV,
// Q A-frags in registers (only 32 regs now), K,V double-buffered fp16.
// smem: k[2] 16KB + v[2] 16KB = 64 KB. Grid 16 x 8; paired q-tiles (bx, 31-bx).
// ---------------------------------------------------------------------------
#define ATT_SMEM 65536

__global__ __launch_bounds__(256, 1) void attn_mma_kernel(float* __restrict__ out)
{
    extern __shared__ float sm[];
    unsigned* kbu[2] = { (unsigned*)sm,             (unsigned*)(sm + 4096) };
    unsigned* vbu[2] = { (unsigned*)(sm + 8192),    (unsigned*)(sm + 12288) };

    const int t    = threadIdx.x;
    const int w    = t >> 5;       // 0..7
    const int lane = t & 31;
    const int g    = lane >> 2;
    const int tig  = lane & 3;
    const int b    = blockIdx.y;
    const int bx   = blockIdx.x;   // 0..15

#pragma unroll 1
    for (int half = 0; half < 2; half++) {
        const int qt = half ? (31 - bx) : bx;   // 128-row q-tile

        // Q A-frags -> registers (rb = w): 8 x uint4 = 32 regs
        const unsigned* qg = g_qh + (size_t)(b * 32 + qt) * 8192;
        uint4 Q[8];
#pragma unroll
        for (int s = 0; s < 8; s++)
            Q[s] = *(const uint4*)(qg + ((w * 8 + s) * 32 + lane) * 4);

        float4 O[16];
#pragma unroll
        for (int ht = 0; ht < 16; ht++) O[ht] = make_float4(0.f, 0.f, 0.f, 0.f);
        float mrow[2] = {-3.0e38f, -3.0e38f};
        float lrow[2] = {0.f, 0.f};
        float aprev[2] = {1.f, 1.f};
        uint4 pa[4];

        const int ntiles = 2 * qt + 2;

        // prologue: K(0)
        {
            const unsigned* kg = g_kh + (size_t)(b * 64) * 4096;
#pragma unroll
            for (int u = 0; u < 4; u++) {
                int idx = u * 256 + t;
                cpasync16(kbu[0] + idx * 4, kg + idx * 4);
            }
            CP_COMMIT();
        }

#pragma unroll 1
        for (int st = 0; st < ntiles; st++) {
            const int p = st & 1;

            cp_wait<0>();          // K(st) + V(st-1) complete
            __syncthreads();

            // issue V(st), K(st+1)
            {
                const unsigned* vg = g_vh + (size_t)(b * 64 + st) * 4096;
#pragma unroll
                for (int u = 0; u < 4; u++) {
                    int idx = u * 256 + t;
                    cpasync16(vbu[p] + idx * 4, vg + idx * 4);
                }
                CP_COMMIT();
            }
            if (st + 1 < ntiles) {
                const unsigned* kg = g_kh + (size_t)(b * 64 + st + 1) * 4096;
#pragma unroll
                for (int u = 0; u < 4; u++) {
                    int idx = u * 256 + t;
                    cpasync16(kbu[p ^ 1] + idx * 4, kg + idx * 4);
                }
                CP_COMMIT();
            }

            // ---- S = Q @ K^T  (16 x 64 per warp; 64 mma) ----
            const unsigned* ksu = kbu[p];
            float4 sa[8];
#pragma unroll
            for (int j = 0; j < 8; j++) sa[j] = make_float4(0.f, 0.f, 0.f, 0.f);
#pragma unroll
            for (int s = 0; s < 8; s++) {
#pragma unroll
                for (int j = 0; j < 8; j++) {
                    uint2 bf = *(const uint2*)(ksu + ((j * 8 + s) * 32 + lane) * 2);
                    mma_f16(sa[j], Q[s], bf);
                }
            }

            // ---- deferred: O *= alpha(st-1); O += P(st-1) @ V(st-1) ----
            if (st > 0) {
#pragma unroll
                for (int ht = 0; ht < 16; ht++) {
                    O[ht].x *= aprev[0]; O[ht].y *= aprev[0];
                    O[ht].z *= aprev[1]; O[ht].w *= aprev[1];
                }
                const unsigned* vsu = vbu[p ^ 1];
#pragma unroll
                for (int kc = 0; kc < 4; kc++) {
#pragma unroll
                    for (int ht = 0; ht < 16; ht++) {
                        uint2 bf = *(const uint2*)(vsu + ((ht * 4 + kc) * 32 + lane) * 2);
                        mma_f16(O[ht], pa[kc], bf);
                    }
                }
            }

            // ---- causal mask (standard layout: .x <-> kv 8j+2tig) ----
            if (st >= 2 * qt) {
                const int rbase = qt * 128 + w * 16 + g;
#pragma unroll
                for (int j = 0; j < 8; j++) {
                    int kv0 = st * 64 + 8 * j + 2 * tig;
                    if (kv0     > rbase)     sa[j].x = -1.0e30f;
                    if (kv0 + 1 > rbase)     sa[j].y = -1.0e30f;
                    if (kv0     > rbase + 8) sa[j].z = -1.0e30f;
                    if (kv0 + 1 > rbase + 8) sa[j].w = -1.0e30f;
                }
            }

            // ---- softmax(st): stats + exp + pack pa ----
#pragma unroll
            for (int h = 0; h < 2; h++) {
                float lm = -3.0e38f;
#pragma unroll
                for (int j = 0; j < 8; j++) {
                    float v0 = h ? sa[j].z : sa[j].x;
                    float v1 = h ? sa[j].w : sa[j].y;
                    lm = fmaxf(lm, fmaxf(v0, v1));
                }
                lm = fmaxf(lm, __shfl_xor_sync(0xffffffffu, lm, 1));
                lm = fmaxf(lm, __shfl_xor_sync(0xffffffffu, lm, 2));
                float mn = fmaxf(mrow[h], lm);
                aprev[h] = __expf(mrow[h] - mn);
                mrow[h] = mn;
                float ls = 0.f;
#pragma unroll
                for (int j = 0; j < 8; j++) {
                    float v0 = h ? sa[j].z : sa[j].x;
                    float v1 = h ? sa[j].w : sa[j].y;
                    v0 = __expf(v0 - mn);
                    v1 = __expf(v1 - mn);
                    if (h) { sa[j].z = v0; sa[j].w = v1; }
                    else   { sa[j].x = v0; sa[j].y = v1; }
                    ls += v0 + v1;
                }
                ls += __shfl_xor_sync(0xffffffffu, ls, 1);
                ls += __shfl_xor_sync(0xffffffffu, ls, 2);
                lrow[h] = lrow[h] * aprev[h] + ls;
            }
            // P A-frags for m16n8k16: {row g cols 2tig.., row g+8, cols+8 ...}
#pragma unroll
            for (int kc = 0; kc < 4; kc++) {
                pa[kc].x = h2pack(sa[2*kc].x,     sa[2*kc].y);
                pa[kc].y = h2pack(sa[2*kc].z,     sa[2*kc].w);
                pa[kc].z = h2pack(sa[2*kc + 1].x, sa[2*kc + 1].y);
                pa[kc].w = h2pack(sa[2*kc + 1].z, sa[2*kc + 1].w);
            }
        }

        // ---- epilogue: final deferred PV, normalize, store ----
        cp_wait<0>();
        __syncthreads();
        {
#pragma unroll
            for (int ht = 0; ht < 16; ht++) {
                O[ht].x *= aprev[0]; O[ht].y *= aprev[0];
                O[ht].z *= aprev[1]; O[ht].w *= aprev[1];
            }
            const unsigned* vsu = vbu[(ntiles - 1) & 1];
#pragma unroll
            for (int kc = 0; kc < 4; kc++) {
#pragma unroll
                for (int ht = 0; ht < 16; ht++) {
                    uint2 bf = *(const uint2*)(vsu + ((ht * 4 + kc) * 32 + lane) * 2);
                    mma_f16(O[ht], pa[kc], bf);
                }
            }
        }
        __syncthreads();

        const float inv0 = 1.0f / lrow[0];
        const float inv1 = 1.0f / lrow[1];
        const int r0 = qt * 128 + w * 16 + g;
        float* o0 = out + ((size_t)b * TT + r0) * HH;
        float* o1 = o0 + 8 * HH;
#pragma unroll
        for (int ht = 0; ht < 16; ht++) {
            int col = ht * 8 + 2 * tig;
            *(float2*)(o0 + col) = make_float2(O[ht].x * inv0, O[ht].y * inv0);
            *(float2*)(o1 + col) = make_float2(O[ht].z * inv1, O[ht].w * inv1);
        }
    }
}

// ---------------------------------------------------------------------------
extern "C" void kernel_launch(void* const* d_in, const int* in_sizes, int n_in,
                              void* d_out, int out_size)
{
    const float* x  = (const float*)d_in[0];
    const float* Wq = (const float*)d_in[1];
    const float* bq = (const float*)d_in[2];
    const float* Wk = (const float*)d_in[3];
    const float* bk = (const float*)d_in[4];
    const float* Wv = (const float*)d_in[5];
    const float* bv = (const float*)d_in[6];
    float* out = (float*)d_out;

    cudaFuncSetAttribute(qkv_mma_kernel,
                         cudaFuncAttributeMaxDynamicSharedMemorySize, QKV_SMEM);
    cudaFuncSetAttribute(attn_mma_kernel,
                         cudaFuncAttributeMaxDynamicSharedMemorySize, ATT_SMEM);

    wpack_kernel<<<dim3(32, 3), 256>>>(Wq, Wk, Wv);
    qkv_mma_kernel<<<dim3(3, MM / 128), 256, QKV_SMEM>>>(x, bq, bk, bv);
    attn_mma_kernel<<<dim3(16, BB), 256, ATT_SMEM>>>(out);
}

// round 14
// speedup vs baseline: 2.4214x; 1.1062x over previous
#include <cuda_runtime.h>
#include <cuda_fp16.h>
#include <cstdint>

#define BB 8
#define TT 4096
#define EE 1024
#define HH 128
#define MM (BB*TT)

// ---------------------------------------------------------------------------
// Scratch (fp16, pre-packed into m16n8k16 fragment order):
// g_qh: per 128-row tile: [rb*8+s][lane][uint4]   (A-frags, s = k16 step)
// g_kh: per 128-kv tile:  [j*8+s][lane][uint2]    j 0..15 (B-frags, S=QK^T)
// g_vh: per 128-kv tile:  [ht*8+kc][lane][uint2]  kc 0..7 (B-frags, O=PV)
// g_wh: W B-frags: [o][kc 0..31][(j*2+s) 0..31][lane][uint2]
// ---------------------------------------------------------------------------
static __device__ __align__(16) unsigned g_qh[(size_t)MM * HH / 2];
static __device__ __align__(16) unsigned g_kh[(size_t)MM * HH / 2];
static __device__ __align__(16) unsigned g_vh[(size_t)MM * HH / 2];
static __device__ __align__(16) unsigned g_wh[3u * EE * HH / 2];

__device__ __forceinline__ unsigned h2pack(float lo, float hi) {
    __half2 h = __floats2half2_rn(lo, hi);
    return *(unsigned*)&h;
}

__device__ __forceinline__ void mma_f16(float4& d, const uint4& a, const uint2& b) {
    asm volatile(
        "mma.sync.aligned.m16n8k16.row.col.f32.f16.f16.f32 "
        "{%0,%1,%2,%3}, {%4,%5,%6,%7}, {%8,%9}, {%0,%1,%2,%3};"
        : "+f"(d.x), "+f"(d.y), "+f"(d.z), "+f"(d.w)
        : "r"(a.x), "r"(a.y), "r"(a.z), "r"(a.w), "r"(b.x), "r"(b.y));
}

__device__ __forceinline__ void cpasync16(void* sdst, const void* gsrc) {
    unsigned s = (unsigned)__cvta_generic_to_shared(sdst);
    asm volatile("cp.async.cg.shared.global [%0], [%1], 16;" :: "r"(s), "l"(gsrc));
}
#define CP_COMMIT() asm volatile("cp.async.commit_group;")
template <int N> __device__ __forceinline__ void cp_wait() {
    asm volatile("cp.async.wait_group %0;" :: "n"(N));
}

// ---------------------------------------------------------------------------
// Kernel 0: one-shot W pre-pack into fp16 B-frag layout. grid (32, 3).
// ---------------------------------------------------------------------------
__global__ __launch_bounds__(256) void wpack_kernel(
    const float* __restrict__ Wq, const float* __restrict__ Wk,
    const float* __restrict__ Wv)
{
    const int kc = blockIdx.x;
    const int o  = blockIdx.y;
    const float* W = (o == 0) ? Wq : (o == 1) ? Wk : Wv;
    unsigned* dst = g_wh + ((size_t)o * 32 + kc) * 2048;
    const int t = threadIdx.x;
#pragma unroll
    for (int u = 0; u < 4; u++) {
        int idx = u * 256 + t;
        int js = idx >> 5, lane = idx & 31;
        int j = js >> 1, s = js & 1;
        int g = lane >> 2, tig = lane & 3;
        int n  = 8 * j + g;
        int k0 = kc * 32 + 16 * s + 2 * tig;
        dst[idx * 2]     = h2pack(W[(size_t)k0 * HH + n],       W[(size_t)(k0 + 1) * HH + n]);
        dst[idx * 2 + 1] = h2pack(W[(size_t)(k0 + 8) * HH + n], W[(size_t)(k0 + 9) * HH + n]);
    }
}

// ---------------------------------------------------------------------------
// Kernel 1: QKV GEMM, fp16 m16n8k16 (R13 mainloop; K/V pack re-indexed for
// 128-row kv tiles). 256 thr, grid (3, MM/128).
// ---------------------------------------------------------------------------
#define XST 36
#define XBUF (128*XST)
#define QKV_SMEM (16896*4)
#define SP 132

__global__ __launch_bounds__(256, 2) void qkv_mma_kernel(
    const float* __restrict__ x,
    const float* __restrict__ bq, const float* __restrict__ bk,
    const float* __restrict__ bv)
{
    extern __shared__ float smq[];
    float* xsb[2] = { smq, smq + XBUF };
    unsigned* whb[2] = { (unsigned*)(smq + 2*XBUF), (unsigned*)(smq + 2*XBUF) + 2048 };
    float* sp = smq;

    const int by = blockIdx.x;
    const int bx = blockIdx.y;
    const float* bias = (by == 0) ? bq : (by == 1) ? bk : bv;
    const unsigned* wp = g_wh + (size_t)by * 32 * 2048;

    const int t    = threadIdx.x;
    const int w    = t >> 5;
    const int lane = t & 31;
    const int g    = lane >> 2;
    const int tig  = lane & 3;
    const int rg   = w & 3;
    const int cg   = w >> 2;
    const int m0   = bx * 128;

    float4 acc[2][8];
#pragma unroll
    for (int i = 0; i < 2; i++)
#pragma unroll
        for (int j = 0; j < 8; j++) acc[i][j] = make_float4(0.f, 0.f, 0.f, 0.f);

#define LOAD_CHUNK(KC, BUF) do {                                              \
        float* xd = xsb[BUF]; unsigned* wd = whb[BUF];                        \
        _Pragma("unroll")                                                     \
        for (int u = 0; u < 4; u++) {                                         \
            int idx = u * 256 + t;                                            \
            int row = idx >> 3, c4 = (idx & 7) * 4;                           \
            cpasync16(xd + row * XST + c4,                                    \
                      x + (size_t)(m0 + row) * EE + (KC) + c4);               \
        }                                                                     \
        _Pragma("unroll")                                                     \
        for (int u = 0; u < 2; u++) {                                         \
            int idx = u * 256 + t;                                            \
            cpasync16(wd + idx * 4, wp + ((KC) >> 5) * 2048 + idx * 4);       \
        }                                                                     \
        CP_COMMIT();                                                          \
    } while (0)

    LOAD_CHUNK(0, 0);

    for (int c = 0; c < 32; c++) {
        const int buf = c & 1;
        if (c < 31) { LOAD_CHUNK((c + 1) * 32, buf ^ 1); cp_wait<1>(); }
        else        { cp_wait<0>(); }
        __syncthreads();

        const float* xb = xsb[buf];
        const uint2* wb2 = (const uint2*)whb[buf];
#pragma unroll
        for (int s = 0; s < 2; s++) {
            const int k0 = 16 * s;
            uint4 a[2];
#pragma unroll
            for (int i = 0; i < 2; i++) {
                const float* r0 = xb + ((2*rg + i)*16 + g)     * XST;
                const float* r1 = xb + ((2*rg + i)*16 + g + 8) * XST;
                float2 v0 = *(const float2*)(r0 + k0 + 2*tig);
                float2 v1 = *(const float2*)(r1 + k0 + 2*tig);
                float2 v2 = *(const float2*)(r0 + k0 + 8 + 2*tig);
                float2 v3 = *(const float2*)(r1 + k0 + 8 + 2*tig);
                a[i].x = h2pack(v0.x, v0.y);
                a[i].y = h2pack(v1.x, v1.y);
                a[i].z = h2pack(v2.x, v2.y);
                a[i].w = h2pack(v3.x, v3.y);
            }
#pragma unroll
            for (int j = 0; j < 8; j++) {
                uint2 bf = wb2[(((cg * 8 + j) * 2 + s) * 32) + lane];
                mma_f16(acc[0][j], a[0], bf);
                mma_f16(acc[1][j], a[1], bf);
            }
        }
        __syncthreads();
    }

    // ---- epilogue: bias (+q scale) -> fp32 smem ----
    const float SCALE = 0.08838834764831845f;
    const float sc = (by == 0) ? SCALE : 1.0f;
#pragma unroll
    for (int i = 0; i < 2; i++) {
        int r0 = rg * 32 + i * 16 + g;
#pragma unroll
        for (int j = 0; j < 8; j++) {
            int c0 = cg * 64 + j * 8 + 2 * tig;
            float b0 = __ldg(bias + c0), b1 = __ldg(bias + c0 + 1);
            float4 a = acc[i][j];
            *(float2*)&sp[r0 * SP + c0]       = make_float2((a.x + b0) * sc, (a.y + b1) * sc);
            *(float2*)&sp[(r0 + 8) * SP + c0] = make_float2((a.z + b0) * sc, (a.w + b1) * sc);
        }
    }
    __syncthreads();

    // ---- pack to fp16 fragment layouts (128-row kv tiles) ----
    if (by == 0) {
        unsigned* dst = g_qh + (size_t)bx * 8192;
#pragma unroll
        for (int s = 0; s < 8; s++) {
            const float* r0 = sp + (w * 16 + g) * SP;
            const float* r1 = sp + (w * 16 + g + 8) * SP;
            uint4 o;
            o.x = h2pack(r0[16*s + 2*tig],     r0[16*s + 2*tig + 1]);
            o.y = h2pack(r1[16*s + 2*tig],     r1[16*s + 2*tig + 1]);
            o.z = h2pack(r0[16*s + 8 + 2*tig], r0[16*s + 8 + 2*tig + 1]);
            o.w = h2pack(r1[16*s + 8 + 2*tig], r1[16*s + 8 + 2*tig + 1]);
            *(uint4*)(dst + ((w * 8 + s) * 32 + lane) * 4) = o;
        }
    } else if (by == 1) {
        unsigned* dst = g_kh + (size_t)bx * 8192;
#pragma unroll
        for (int it = 0; it < 16; it++) {
            int idx = w * 16 + it;            // 0..127 = j*8+s
            int j = idx >> 3, s = idx & 7;
            const float* r = sp + (8 * j + g) * SP;
            unsigned w0 = h2pack(r[16*s + 2*tig],     r[16*s + 2*tig + 1]);
            unsigned w1 = h2pack(r[16*s + 8 + 2*tig], r[16*s + 8 + 2*tig + 1]);
            *(uint2*)(dst + (idx * 32 + lane) * 2) = make_uint2(w0, w1);
        }
    } else {
        unsigned* dst = g_vh + (size_t)bx * 8192;
#pragma unroll
        for (int it = 0; it < 16; it++) {
            int idx = w * 16 + it;            // 0..127 = ht*8+kc
            int ht = idx >> 3, kc = idx & 7;
            int n = 8 * ht + g;
            int r0 = 16 * kc + 2 * tig;
            unsigned w0 = h2pack(sp[r0 * SP + n],       sp[(r0 + 1) * SP + n]);
            unsigned w1 = h2pack(sp[(r0 + 8) * SP + n], sp[(r0 + 9) * SP + n]);
            *(uint2*)(dst + (idx * 32 + lane) * 2) = make_uint2(w0, w1);
        }
    }
}

// ---------------------------------------------------------------------------
// Kernel 2: flash attention, fp16, kv-tile = 128 (fixed costs amortized 2x).
// Deferred-PV, Q in registers. K,V double-buffered: smem 128 KB, 1 CTA/SM.
// Grid 16 x 8; CTA does q-tiles (bx, 31-bx): 33 kv-iters each (balanced).
// ---------------------------------------------------------------------------
#define ATT_SMEM 131072

__global__ __launch_bounds__(256, 1) void attn_mma_kernel(float* __restrict__ out)
{
    extern __shared__ float sm[];
    unsigned* kbu[2] = { (unsigned*)sm,          (unsigned*)sm + 8192 };
    unsigned* vbu[2] = { (unsigned*)sm + 16384,  (unsigned*)sm + 24576 };

    const int t    = threadIdx.x;
    const int w    = t >> 5;       // 0..7
    const int lane = t & 31;
    const int g    = lane >> 2;
    const int tig  = lane & 3;
    const int b    = blockIdx.y;
    const int bx   = blockIdx.x;   // 0..15

#pragma unroll 1
    for (int half = 0; half < 2; half++) {
        const int qt = half ? (31 - bx) : bx;   // 128-row q-tile

        // Q A-frags -> registers (rb = w): 8 x uint4 = 32 regs
        const unsigned* qg = g_qh + (size_t)(b * 32 + qt) * 8192;
        uint4 Q[8];
#pragma unroll
        for (int s = 0; s < 8; s++)
            Q[s] = *(const uint4*)(qg + ((w * 8 + s) * 32 + lane) * 4);

        float4 O[16];
#pragma unroll
        for (int ht = 0; ht < 16; ht++) O[ht] = make_float4(0.f, 0.f, 0.f, 0.f);
        float mrow[2] = {-3.0e38f, -3.0e38f};
        float lrow[2] = {0.f, 0.f};
        float aprev[2] = {1.f, 1.f};
        uint4 pa[8];

        const int ntiles = qt + 1;

        // prologue: K(0)
        {
            const unsigned* kg = g_kh + (size_t)(b * 32) * 8192;
#pragma unroll
            for (int u = 0; u < 8; u++) {
                int idx = u * 256 + t;
                cpasync16(kbu[0] + idx * 4, kg + idx * 4);
            }
            CP_COMMIT();
        }

#pragma unroll 1
        for (int st = 0; st < ntiles; st++) {
            const int p = st & 1;

            cp_wait<0>();          // K(st) + V(st-1) complete
            __syncthreads();

            // issue V(st), K(st+1)
            {
                const unsigned* vg = g_vh + (size_t)(b * 32 + st) * 8192;
#pragma unroll
                for (int u = 0; u < 8; u++) {
                    int idx = u * 256 + t;
                    cpasync16(vbu[p] + idx * 4, vg + idx * 4);
                }
                CP_COMMIT();
            }
            if (st + 1 < ntiles) {
                const unsigned* kg = g_kh + (size_t)(b * 32 + st + 1) * 8192;
#pragma unroll
                for (int u = 0; u < 8; u++) {
                    int idx = u * 256 + t;
                    cpasync16(kbu[p ^ 1] + idx * 4, kg + idx * 4);
                }
                CP_COMMIT();
            }

            // ---- S = Q @ K^T  (16 x 128 per warp; 128 mma) ----
            const unsigned* ksu = kbu[p];
            float4 sa[16];
#pragma unroll
            for (int j = 0; j < 16; j++) sa[j] = make_float4(0.f, 0.f, 0.f, 0.f);
#pragma unroll
            for (int s = 0; s < 8; s++) {
#pragma unroll
                for (int j = 0; j < 16; j++) {
                    uint2 bf = *(const uint2*)(ksu + ((j * 8 + s) * 32 + lane) * 2);
                    mma_f16(sa[j], Q[s], bf);
                }
            }

            // ---- deferred: O *= alpha(st-1); O += P(st-1) @ V(st-1) ----
            if (st > 0) {
#pragma unroll
                for (int ht = 0; ht < 16; ht++) {
                    O[ht].x *= aprev[0]; O[ht].y *= aprev[0];
                    O[ht].z *= aprev[1]; O[ht].w *= aprev[1];
                }
                const unsigned* vsu = vbu[p ^ 1];
#pragma unroll
                for (int kc = 0; kc < 8; kc++) {
#pragma unroll
                    for (int ht = 0; ht < 16; ht++) {
                        uint2 bf = *(const uint2*)(vsu + ((ht * 8 + kc) * 32 + lane) * 2);
                        mma_f16(O[ht], pa[kc], bf);
                    }
                }
            }

            // ---- causal mask: only the diagonal tile (st == qt) ----
            if (st == qt) {
                const int rbase = w * 16 + g;
#pragma unroll
                for (int j = 0; j < 16; j++) {
                    int kv0 = 8 * j + 2 * tig;
                    if (kv0     > rbase)     sa[j].x = -1.0e30f;
                    if (kv0 + 1 > rbase)     sa[j].y = -1.0e30f;
                    if (kv0     > rbase + 8) sa[j].z = -1.0e30f;
                    if (kv0 + 1 > rbase + 8) sa[j].w = -1.0e30f;
                }
            }

            // ---- softmax(st): stats + exp + pack pa ----
#pragma unroll
            for (int h = 0; h < 2; h++) {
                float lm = -3.0e38f;
#pragma unroll
                for (int j = 0; j < 16; j++) {
                    float v0 = h ? sa[j].z : sa[j].x;
                    float v1 = h ? sa[j].w : sa[j].y;
                    lm = fmaxf(lm, fmaxf(v0, v1));
                }
                lm = fmaxf(lm, __shfl_xor_sync(0xffffffffu, lm, 1));
                lm = fmaxf(lm, __shfl_xor_sync(0xffffffffu, lm, 2));
                float mn = fmaxf(mrow[h], lm);
                aprev[h] = __expf(mrow[h] - mn);
                mrow[h] = mn;
                float ls = 0.f;
#pragma unroll
                for (int j = 0; j < 16; j++) {
                    float v0 = h ? sa[j].z : sa[j].x;
                    float v1 = h ? sa[j].w : sa[j].y;
                    v0 = __expf(v0 - mn);
                    v1 = __expf(v1 - mn);
                    if (h) { sa[j].z = v0; sa[j].w = v1; }
                    else   { sa[j].x = v0; sa[j].y = v1; }
                    ls += v0 + v1;
                }
                ls += __shfl_xor_sync(0xffffffffu, ls, 1);
                ls += __shfl_xor_sync(0xffffffffu, ls, 2);
                lrow[h] = lrow[h] * aprev[h] + ls;
            }
#pragma unroll
            for (int kc = 0; kc < 8; kc++) {
                pa[kc].x = h2pack(sa[2*kc].x,     sa[2*kc].y);
                pa[kc].y = h2pack(sa[2*kc].z,     sa[2*kc].w);
                pa[kc].z = h2pack(sa[2*kc + 1].x, sa[2*kc + 1].y);
                pa[kc].w = h2pack(sa[2*kc + 1].z, sa[2*kc + 1].w);
            }
        }

        // ---- epilogue: final deferred PV, normalize, store ----
        cp_wait<0>();
        __syncthreads();
        {
#pragma unroll
            for (int ht = 0; ht < 16; ht++) {
                O[ht].x *= aprev[0]; O[ht].y *= aprev[0];
                O[ht].z *= aprev[1]; O[ht].w *= aprev[1];
            }
            const unsigned* vsu = vbu[(ntiles - 1) & 1];
#pragma unroll
            for (int kc = 0; kc < 8; kc++) {
#pragma unroll
                for (int ht = 0; ht < 16; ht++) {
                    uint2 bf = *(const uint2*)(vsu + ((ht * 8 + kc) * 32 + lane) * 2);
                    mma_f16(O[ht], pa[kc], bf);
                }
            }
        }
        __syncthreads();

        const float inv0 = 1.0f / lrow[0];
        const float inv1 = 1.0f / lrow[1];
        const int r0 = qt * 128 + w * 16 + g;
        float* o0 = out + ((size_t)b * TT + r0) * HH;
        float* o1 = o0 + 8 * HH;
#pragma unroll
        for (int ht = 0; ht < 16; ht++) {
            int col = ht * 8 + 2 * tig;
            *(float2*)(o0 + col) = make_float2(O[ht].x * inv0, O[ht].y * inv0);
            *(float2*)(o1 + col) = make_float2(O[ht].z * inv1, O[ht].w * inv1);
        }
    }
}

// ---------------------------------------------------------------------------
extern "C" void kernel_launch(void* const* d_in, const int* in_sizes, int n_in,
                              void* d_out, int out_size)
{
    const float* x  = (const float*)d_in[0];
    const float* Wq = (const float*)d_in[1];
    const float* bq = (const float*)d_in[2];
    const float* Wk = (const float*)d_in[3];
    const float* bk = (const float*)d_in[4];
    const float* Wv = (const float*)d_in[5];
    const float* bv = (const float*)d_in[6];
    float* out = (float*)d_out;

    cudaFuncSetAttribute(qkv_mma_kernel,
                         cudaFuncAttributeMaxDynamicSharedMemorySize, QKV_SMEM);
    cudaFuncSetAttribute(attn_mma_kernel,
                         cudaFuncAttributeMaxDynamicSharedMemorySize, ATT_SMEM);

    wpack_kernel<<<dim3(32, 3), 256>>>(Wq, Wk, Wv);
    qkv_mma_kernel<<<dim3(3, MM / 128), 256, QKV_SMEM>>>(x, bq, bk, bv);
    attn_mma_kernel<<<dim3(16, BB), 256, ATT_SMEM>>>(out);
}

// round 15
// speedup vs baseline: 2.4359x; 1.0060x over previous
#include <cuda_runtime.h>
#include <cuda_fp16.h>
#include <cstdint>

#define BB 8
#define TT 4096
#define EE 1024
#define HH 128
#define MM (BB*TT)

// ---------------------------------------------------------------------------
// Scratch (fp16, pre-packed into m16n8k16 fragment order):
// g_qh: per 128-row tile: [rb*8+s][lane][uint4]   (A-frags, s = k16 step)
// g_kh: per 128-kv tile:  [j*8+s][lane][uint2]    j 0..15 (B-frags, S=QK^T)
// g_vh: per 128-kv tile:  [ht*8+kc][lane][uint2]  kc 0..7 (B-frags, O=PV)
// g_wh: W B-frags: [o][kc 0..31][(j*2+s) 0..31][lane][uint2]
// ---------------------------------------------------------------------------
static __device__ __align__(16) unsigned g_qh[(size_t)MM * HH / 2];
static __device__ __align__(16) unsigned g_kh[(size_t)MM * HH / 2];
static __device__ __align__(16) unsigned g_vh[(size_t)MM * HH / 2];
static __device__ __align__(16) unsigned g_wh[3u * EE * HH / 2];

__device__ __forceinline__ unsigned h2pack(float lo, float hi) {
    __half2 h = __floats2half2_rn(lo, hi);
    return *(unsigned*)&h;
}

__device__ __forceinline__ void mma_f16(float4& d, const uint4& a, const uint2& b) {
    asm volatile(
        "mma.sync.aligned.m16n8k16.row.col.f32.f16.f16.f32 "
        "{%0,%1,%2,%3}, {%4,%5,%6,%7}, {%8,%9}, {%0,%1,%2,%3};"
        : "+f"(d.x), "+f"(d.y), "+f"(d.z), "+f"(d.w)
        : "r"(a.x), "r"(a.y), "r"(a.z), "r"(a.w), "r"(b.x), "r"(b.y));
}

__device__ __forceinline__ void cpasync16(void* sdst, const void* gsrc) {
    unsigned s = (unsigned)__cvta_generic_to_shared(sdst);
    asm volatile("cp.async.cg.shared.global [%0], [%1], 16;" :: "r"(s), "l"(gsrc));
}
#define CP_COMMIT() asm volatile("cp.async.commit_group;")
template <int N> __device__ __forceinline__ void cp_wait() {
    asm volatile("cp.async.wait_group %0;" :: "n"(N));
}

// ---------------------------------------------------------------------------
// Kernel 0: one-shot W pre-pack into fp16 B-frag layout. grid (32, 3).
// ---------------------------------------------------------------------------
__global__ __launch_bounds__(256) void wpack_kernel(
    const float* __restrict__ Wq, const float* __restrict__ Wk,
    const float* __restrict__ Wv)
{
    const int kc = blockIdx.x;
    const int o  = blockIdx.y;
    const float* W = (o == 0) ? Wq : (o == 1) ? Wk : Wv;
    unsigned* dst = g_wh + ((size_t)o * 32 + kc) * 2048;
    const int t = threadIdx.x;
#pragma unroll
    for (int u = 0; u < 4; u++) {
        int idx = u * 256 + t;
        int js = idx >> 5, lane = idx & 31;
        int j = js >> 1, s = js & 1;
        int g = lane >> 2, tig = lane & 3;
        int n  = 8 * j + g;
        int k0 = kc * 32 + 16 * s + 2 * tig;
        dst[idx * 2]     = h2pack(W[(size_t)k0 * HH + n],       W[(size_t)(k0 + 1) * HH + n]);
        dst[idx * 2 + 1] = h2pack(W[(size_t)(k0 + 8) * HH + n], W[(size_t)(k0 + 9) * HH + n]);
    }
}

// ---------------------------------------------------------------------------
// Kernel 1: QKV GEMM, fp16 m16n8k16 (R13 mainloop; K/V pack re-indexed for
// 128-row kv tiles). 256 thr, grid (3, MM/128).
// ---------------------------------------------------------------------------
#define XST 36
#define XBUF (128*XST)
#define QKV_SMEM (16896*4)
#define SP 132

__global__ __launch_bounds__(256, 2) void qkv_mma_kernel(
    const float* __restrict__ x,
    const float* __restrict__ bq, const float* __restrict__ bk,
    const float* __restrict__ bv)
{
    extern __shared__ float smq[];
    float* xsb[2] = { smq, smq + XBUF };
    unsigned* whb[2] = { (unsigned*)(smq + 2*XBUF), (unsigned*)(smq + 2*XBUF) + 2048 };
    float* sp = smq;

    const int by = blockIdx.x;
    const int bx = blockIdx.y;
    const float* bias = (by == 0) ? bq : (by == 1) ? bk : bv;
    const unsigned* wp = g_wh + (size_t)by * 32 * 2048;

    const int t    = threadIdx.x;
    const int w    = t >> 5;
    const int lane = t & 31;
    const int g    = lane >> 2;
    const int tig  = lane & 3;
    const int rg   = w & 3;
    const int cg   = w >> 2;
    const int m0   = bx * 128;

    float4 acc[2][8];
#pragma unroll
    for (int i = 0; i < 2; i++)
#pragma unroll
        for (int j = 0; j < 8; j++) acc[i][j] = make_float4(0.f, 0.f, 0.f, 0.f);

#define LOAD_CHUNK(KC, BUF) do {                                              \
        float* xd = xsb[BUF]; unsigned* wd = whb[BUF];                        \
        _Pragma("unroll")                                                     \
        for (int u = 0; u < 4; u++) {                                         \
            int idx = u * 256 + t;                                            \
            int row = idx >> 3, c4 = (idx & 7) * 4;                           \
            cpasync16(xd + row * XST + c4,                                    \
                      x + (size_t)(m0 + row) * EE + (KC) + c4);               \
        }                                                                     \
        _Pragma("unroll")                                                     \
        for (int u = 0; u < 2; u++) {                                         \
            int idx = u * 256 + t;                                            \
            cpasync16(wd + idx * 4, wp + ((KC) >> 5) * 2048 + idx * 4);       \
        }                                                                     \
        CP_COMMIT();                                                          \
    } while (0)

    LOAD_CHUNK(0, 0);

    for (int c = 0; c < 32; c++) {
        const int buf = c & 1;
        if (c < 31) { LOAD_CHUNK((c + 1) * 32, buf ^ 1); cp_wait<1>(); }
        else        { cp_wait<0>(); }
        __syncthreads();

        const float* xb = xsb[buf];
        const uint2* wb2 = (const uint2*)whb[buf];
#pragma unroll
        for (int s = 0; s < 2; s++) {
            const int k0 = 16 * s;
            uint4 a[2];
#pragma unroll
            for (int i = 0; i < 2; i++) {
                const float* r0 = xb + ((2*rg + i)*16 + g)     * XST;
                const float* r1 = xb + ((2*rg + i)*16 + g + 8) * XST;
                float2 v0 = *(const float2*)(r0 + k0 + 2*tig);
                float2 v1 = *(const float2*)(r1 + k0 + 2*tig);
                float2 v2 = *(const float2*)(r0 + k0 + 8 + 2*tig);
                float2 v3 = *(const float2*)(r1 + k0 + 8 + 2*tig);
                a[i].x = h2pack(v0.x, v0.y);
                a[i].y = h2pack(v1.x, v1.y);
                a[i].z = h2pack(v2.x, v2.y);
                a[i].w = h2pack(v3.x, v3.y);
            }
#pragma unroll
            for (int j = 0; j < 8; j++) {
                uint2 bf = wb2[(((cg * 8 + j) * 2 + s) * 32) + lane];
                mma_f16(acc[0][j], a[0], bf);
                mma_f16(acc[1][j], a[1], bf);
            }
        }
        __syncthreads();
    }

    // ---- epilogue: bias (+q scale) -> fp32 smem ----
    const float SCALE = 0.08838834764831845f;
    const float sc = (by == 0) ? SCALE : 1.0f;
#pragma unroll
    for (int i = 0; i < 2; i++) {
        int r0 = rg * 32 + i * 16 + g;
#pragma unroll
        for (int j = 0; j < 8; j++) {
            int c0 = cg * 64 + j * 8 + 2 * tig;
            float b0 = __ldg(bias + c0), b1 = __ldg(bias + c0 + 1);
            float4 a = acc[i][j];
            *(float2*)&sp[r0 * SP + c0]       = make_float2((a.x + b0) * sc, (a.y + b1) * sc);
            *(float2*)&sp[(r0 + 8) * SP + c0] = make_float2((a.z + b0) * sc, (a.w + b1) * sc);
        }
    }
    __syncthreads();

    // ---- pack to fp16 fragment layouts (128-row kv tiles) ----
    if (by == 0) {
        unsigned* dst = g_qh + (size_t)bx * 8192;
#pragma unroll
        for (int s = 0; s < 8; s++) {
            const float* r0 = sp + (w * 16 + g) * SP;
            const float* r1 = sp + (w * 16 + g + 8) * SP;
            uint4 o;
            o.x = h2pack(r0[16*s + 2*tig],     r0[16*s + 2*tig + 1]);
            o.y = h2pack(r1[16*s + 2*tig],     r1[16*s + 2*tig + 1]);
            o.z = h2pack(r0[16*s + 8 + 2*tig], r0[16*s + 8 + 2*tig + 1]);
            o.w = h2pack(r1[16*s + 8 + 2*tig], r1[16*s + 8 + 2*tig + 1]);
            *(uint4*)(dst + ((w * 8 + s) * 32 + lane) * 4) = o;
        }
    } else if (by == 1) {
        unsigned* dst = g_kh + (size_t)bx * 8192;
#pragma unroll
        for (int it = 0; it < 16; it++) {
            int idx = w * 16 + it;            // 0..127 = j*8+s
            int j = idx >> 3, s = idx & 7;
            const float* r = sp + (8 * j + g) * SP;
            unsigned w0 = h2pack(r[16*s + 2*tig],     r[16*s + 2*tig + 1]);
            unsigned w1 = h2pack(r[16*s + 8 + 2*tig], r[16*s + 8 + 2*tig + 1]);
            *(uint2*)(dst + (idx * 32 + lane) * 2) = make_uint2(w0, w1);
        }
    } else {
        unsigned* dst = g_vh + (size_t)bx * 8192;
#pragma unroll
        for (int it = 0; it < 16; it++) {
            int idx = w * 16 + it;            // 0..127 = ht*8+kc
            int ht = idx >> 3, kc = idx & 7;
            int n = 8 * ht + g;
            int r0 = 16 * kc + 2 * tig;
            unsigned w0 = h2pack(sp[r0 * SP + n],       sp[(r0 + 1) * SP + n]);
            unsigned w1 = h2pack(sp[(r0 + 8) * SP + n], sp[(r0 + 9) * SP + n]);
            *(uint2*)(dst + (idx * 32 + lane) * 2) = make_uint2(w0, w1);
        }
    }
}

// ---------------------------------------------------------------------------
// Kernel 2: flash attention, fp16, kv-tile = 128 (fixed costs amortized 2x).
// Deferred-PV, Q in registers. K,V double-buffered: smem 128 KB, 1 CTA/SM.
// Grid 16 x 8; CTA does q-tiles (bx, 31-bx): 33 kv-iters each (balanced).
// ---------------------------------------------------------------------------
#define ATT_SMEM 131072

__global__ __launch_bounds__(256, 1) void attn_mma_kernel(float* __restrict__ out)
{
    extern __shared__ float sm[];
    unsigned* kbu[2] = { (unsigned*)sm,          (unsigned*)sm + 8192 };
    unsigned* vbu[2] = { (unsigned*)sm + 16384,  (unsigned*)sm + 24576 };

    const int t    = threadIdx.x;
    const int w    = t >> 5;       // 0..7
    const int lane = t & 31;
    const int g    = lane >> 2;
    const int tig  = lane & 3;
    const int b    = blockIdx.y;
    const int bx   = blockIdx.x;   // 0..15

#pragma unroll 1
    for (int half = 0; half < 2; half++) {
        const int qt = half ? (31 - bx) : bx;   // 128-row q-tile

        // Q A-frags -> registers (rb = w): 8 x uint4 = 32 regs
        const unsigned* qg = g_qh + (size_t)(b * 32 + qt) * 8192;
        uint4 Q[8];
#pragma unroll
        for (int s = 0; s < 8; s++)
            Q[s] = *(const uint4*)(qg + ((w * 8 + s) * 32 + lane) * 4);

        float4 O[16];
#pragma unroll
        for (int ht = 0; ht < 16; ht++) O[ht] = make_float4(0.f, 0.f, 0.f, 0.f);
        float mrow[2] = {-3.0e38f, -3.0e38f};
        float lrow[2] = {0.f, 0.f};
        float aprev[2] = {1.f, 1.f};
        uint4 pa[8];

        const int ntiles = qt + 1;

        // prologue: K(0)
        {
            const unsigned* kg = g_kh + (size_t)(b * 32) * 8192;
#pragma unroll
            for (int u = 0; u < 8; u++) {
                int idx = u * 256 + t;
                cpasync16(kbu[0] + idx * 4, kg + idx * 4);
            }
            CP_COMMIT();
        }

#pragma unroll 1
        for (int st = 0; st < ntiles; st++) {
            const int p = st & 1;

            cp_wait<0>();          // K(st) + V(st-1) complete
            __syncthreads();

            // issue V(st), K(st+1)
            {
                const unsigned* vg = g_vh + (size_t)(b * 32 + st) * 8192;
#pragma unroll
                for (int u = 0; u < 8; u++) {
                    int idx = u * 256 + t;
                    cpasync16(vbu[p] + idx * 4, vg + idx * 4);
                }
                CP_COMMIT();
            }
            if (st + 1 < ntiles) {
                const unsigned* kg = g_kh + (size_t)(b * 32 + st + 1) * 8192;
#pragma unroll
                for (int u = 0; u < 8; u++) {
                    int idx = u * 256 + t;
                    cpasync16(kbu[p ^ 1] + idx * 4, kg + idx * 4);
                }
                CP_COMMIT();
            }

            // ---- S = Q @ K^T  (16 x 128 per warp; 128 mma) ----
            const unsigned* ksu = kbu[p];
            float4 sa[16];
#pragma unroll
            for (int j = 0; j < 16; j++) sa[j] = make_float4(0.f, 0.f, 0.f, 0.f);
#pragma unroll
            for (int s = 0; s < 8; s++) {
#pragma unroll
                for (int j = 0; j < 16; j++) {
                    uint2 bf = *(const uint2*)(ksu + ((j * 8 + s) * 32 + lane) * 2);
                    mma_f16(sa[j], Q[s], bf);
                }
            }

            // ---- deferred: O *= alpha(st-1); O += P(st-1) @ V(st-1) ----
            if (st > 0) {
#pragma unroll
                for (int ht = 0; ht < 16; ht++) {
                    O[ht].x *= aprev[0]; O[ht].y *= aprev[0];
                    O[ht].z *= aprev[1]; O[ht].w *= aprev[1];
                }
                const unsigned* vsu = vbu[p ^ 1];
#pragma unroll
                for (int kc = 0; kc < 8; kc++) {
#pragma unroll
                    for (int ht = 0; ht < 16; ht++) {
                        uint2 bf = *(const uint2*)(vsu + ((ht * 8 + kc) * 32 + lane) * 2);
                        mma_f16(O[ht], pa[kc], bf);
                    }
                }
            }

            // ---- causal mask: only the diagonal tile (st == qt) ----
            if (st == qt) {
                const int rbase = w * 16 + g;
#pragma unroll
                for (int j = 0; j < 16; j++) {
                    int kv0 = 8 * j + 2 * tig;
                    if (kv0     > rbase)     sa[j].x = -1.0e30f;
                    if (kv0 + 1 > rbase)     sa[j].y = -1.0e30f;
                    if (kv0     > rbase + 8) sa[j].z = -1.0e30f;
                    if (kv0 + 1 > rbase + 8) sa[j].w = -1.0e30f;
                }
            }

            // ---- softmax(st): stats + exp + pack pa ----
#pragma unroll
            for (int h = 0; h < 2; h++) {
                float lm = -3.0e38f;
#pragma unroll
                for (int j = 0; j < 16; j++) {
                    float v0 = h ? sa[j].z : sa[j].x;
                    float v1 = h ? sa[j].w : sa[j].y;
                    lm = fmaxf(lm, fmaxf(v0, v1));
                }
                lm = fmaxf(lm, __shfl_xor_sync(0xffffffffu, lm, 1));
                lm = fmaxf(lm, __shfl_xor_sync(0xffffffffu, lm, 2));
                float mn = fmaxf(mrow[h], lm);
                aprev[h] = __expf(mrow[h] - mn);
                mrow[h] = mn;
                float ls = 0.f;
#pragma unroll
                for (int j = 0; j < 16; j++) {
                    float v0 = h ? sa[j].z : sa[j].x;
                    float v1 = h ? sa[j].w : sa[j].y;
                    v0 = __expf(v0 - mn);
                    v1 = __expf(v1 - mn);
                    if (h) { sa[j].z = v0; sa[j].w = v1; }
                    else   { sa[j].x = v0; sa[j].y = v1; }
                    ls += v0 + v1;
                }
                ls += __shfl_xor_sync(0xffffffffu, ls, 1);
                ls += __shfl_xor_sync(0xffffffffu, ls, 2);
                lrow[h] = lrow[h] * aprev[h] + ls;
            }
#pragma unroll
            for (int kc = 0; kc < 8; kc++) {
                pa[kc].x = h2pack(sa[2*kc].x,     sa[2*kc].y);
                pa[kc].y = h2pack(sa[2*kc].z,     sa[2*kc].w);
                pa[kc].z = h2pack(sa[2*kc + 1].x, sa[2*kc + 1].y);
                pa[kc].w = h2pack(sa[2*kc + 1].z, sa[2*kc + 1].w);
            }
        }

        // ---- epilogue: final deferred PV, normalize, store ----
        cp_wait<0>();
        __syncthreads();
        {
#pragma unroll
            for (int ht = 0; ht < 16; ht++) {
                O[ht].x *= aprev[0]; O[ht].y *= aprev[0];
                O[ht].z *= aprev[1]; O[ht].w *= aprev[1];
            }
            const unsigned* vsu = vbu[(ntiles - 1) & 1];
#pragma unroll
            for (int kc = 0; kc < 8; kc++) {
#pragma unroll
                for (int ht = 0; ht < 16; ht++) {
                    uint2 bf = *(const uint2*)(vsu + ((ht * 8 + kc) * 32 + lane) * 2);
                    mma_f16(O[ht], pa[kc], bf);
                }
            }
        }
        __syncthreads();

        const float inv0 = 1.0f / lrow[0];
        const float inv1 = 1.0f / lrow[1];
        const int r0 = qt * 128 + w * 16 + g;
        float* o0 = out + ((size_t)b * TT + r0) * HH;
        float* o1 = o0 + 8 * HH;
#pragma unroll
        for (int ht = 0; ht < 16; ht++) {
            int col = ht * 8 + 2 * tig;
            *(float2*)(o0 + col) = make_float2(O[ht].x * inv0, O[ht].y * inv0);
            *(float2*)(o1 + col) = make_float2(O[ht].z * inv1, O[ht].w * inv1);
        }
    }
}

// ---------------------------------------------------------------------------
extern "C" void kernel_launch(void* const* d_in, const int* in_sizes, int n_in,
                              void* d_out, int out_size)
{
    const float* x  = (const float*)d_in[0];
    const float* Wq = (const float*)d_in[1];
    const float* bq = (const float*)d_in[2];
    const float* Wk = (const float*)d_in[3];
    const float* bk = (const float*)d_in[4];
    const float* Wv = (const float*)d_in[5];
    const float* bv = (const float*)d_in[6];
    float* out = (float*)d_out;

    cudaFuncSetAttribute(qkv_mma_kernel,
                         cudaFuncAttributeMaxDynamicSharedMemorySize, QKV_SMEM);
    cudaFuncSetAttribute(attn_mma_kernel,
                         cudaFuncAttributeMaxDynamicSharedMemorySize, ATT_SMEM);

    wpack_kernel<<<dim3(32, 3), 256>>>(Wq, Wk, Wv);
    qkv_mma_kernel<<<dim3(3, MM / 128), 256, QKV_SMEM>>>(x, bq, bk, bv);
    attn_mma_kernel<<<dim3(16, BB), 256, ATT_SMEM>>>(out);
}